// round 16
// baseline (speedup 1.0000x reference)
#include <cuda_runtime.h>
#include <cuda_fp16.h>
#include <cstdint>

#define NN 100000
#define H 128
#define NE 1600000
#define NL 3
#define OUTC 32
#define HMID 64
#define TILE_M 128

// ---------------- scratch ----------------
__device__ __half g_hsh[4][(size_t)NN * H];    // half h: 0=hu0 1=hu1 2=hi0 3=hi1 (ping-pong)
__device__ __half g_aggh[2][(size_t)NN * H];   // half agg outputs (0: user-src, 1: item-src)
__device__ __half g_xh[2][(size_t)NN * H];     // half x_user / x_item
__device__ __half g_wh[237568];                // transposed half weights [n][k]
#define BT_ENC_U 196608
#define BT_ENC_I 212992
#define BT_CLS   229376

__device__ int g_rowptr[2][NN + 1];
__device__ int g_colv[2][NE];
__device__ int g_rank[2][NE];                  // per-edge within-row slot (from hist atomic)
__device__ int g_cnt[2][NN];                   // zero-initialized at load; re-zeroed by scan1
__device__ int g_bsums[2][256];

__device__ __forceinline__ const __half* pickh(int id) {
    if (id < 4) return g_hsh[id];
    if (id < 6) return g_aggh[id - 4];
    return g_xh[id - 6];
}

__device__ __forceinline__ void mma_f16(float c[4], const uint32_t a[4], const uint32_t b[2]) {
    asm volatile(
        "mma.sync.aligned.m16n8k16.row.col.f32.f16.f16.f32 "
        "{%0,%1,%2,%3}, {%4,%5,%6,%7}, {%8,%9}, {%0,%1,%2,%3};"
        : "+f"(c[0]), "+f"(c[1]), "+f"(c[2]), "+f"(c[3])
        : "r"(a[0]), "r"(a[1]), "r"(a[2]), "r"(a[3]), "r"(b[0]), "r"(b[1]));
}
__device__ __forceinline__ void ldsm4(uint32_t& r0, uint32_t& r1, uint32_t& r2, uint32_t& r3,
                                      uint32_t addr) {
    asm volatile("ldmatrix.sync.aligned.m8n8.x4.shared.b16 {%0,%1,%2,%3}, [%4];"
                 : "=r"(r0), "=r"(r1), "=r"(r2), "=r"(r3) : "r"(addr));
}
__device__ __forceinline__ void cp16(uint32_t dst, const void* src) {
    asm volatile("cp.async.ca.shared.global [%0], [%1], 16;" :: "r"(dst), "l"(src));
}

struct H4 { __half2 a, b; };

// ---------------- mega front: prep_w + prep_x + hist(+rank) ----------------
#define PW_B 928
#define PX_B 12500
#define HI_B 1563
__global__ void __launch_bounds__(256) k_front(
    const float* __restrict__ Wl_ui, const float* __restrict__ Wr_ui,
    const float* __restrict__ Wl_iu, const float* __restrict__ Wr_iu,
    const float* __restrict__ eWu, const float* __restrict__ eWi,
    const float* __restrict__ cW1,
    const float* __restrict__ xu, const float* __restrict__ xi,
    const int* __restrict__ du, const int* __restrict__ di) {
    int b = blockIdx.x, tid = threadIdx.x;
    if (b < PW_B) {
        int idx = b * 256 + tid;
        if (idx >= 237568) return;
        float v;
        if (idx < 196608) {
            int c = idx >> 15, r = idx & 32767, n = r >> 8, k = r & 255;
            int l = c >> 1, side = c & 1;
            const float* WL = side ? Wl_ui : Wl_iu;
            const float* WR = side ? Wr_ui : Wr_iu;
            v = (k < 128) ? WL[l * 16384 + k * 128 + n] : WR[l * 16384 + (k - 128) * 128 + n];
        } else if (idx < 229376) {
            int r = idx - 196608, e = r >> 14, rr = r & 16383, n = rr >> 7, k = rr & 127;
            v = (e ? eWi : eWu)[k * 128 + n];
        } else {
            int r = idx - 229376, n = r >> 7, k = r & 127;
            v = cW1[k * 64 + n];
        }
        g_wh[idx] = __float2half(v);
    } else if (b < PW_B + 2 * PX_B) {
        int bb = b - PW_B;
        int et = bb >= PX_B;
        int i = (bb - et * PX_B) * 256 + tid;
        if (i >= NN * 32) return;
        const float4* src = (const float4*)(et ? xi : xu);
        float4 v = src[i];
        H4 h;
        h.a = __floats2half2_rn(v.x, v.y);
        h.b = __floats2half2_rn(v.z, v.w);
        ((H4*)g_xh[et])[i] = h;
    } else {
        int bb = b - (PW_B + 2 * PX_B);
        int et = bb >= HI_B;
        const int* dst = et ? di : du;
        int base = (bb - et * HI_B) * 1024 + tid * 4;
        if (base + 4 <= NE) {
            int4 d4 = *(const int4*)(dst + base);
            int4 r4;
            r4.x = atomicAdd(&g_cnt[et][d4.x], 1);
            r4.y = atomicAdd(&g_cnt[et][d4.y], 1);
            r4.z = atomicAdd(&g_cnt[et][d4.z], 1);
            r4.w = atomicAdd(&g_cnt[et][d4.w], 1);
            *(int4*)(g_rank[et] + base) = r4;
        } else {
            for (int j = base; j < base + 4 && j < NE; j++)
                g_rank[et][j] = atomicAdd(&g_cnt[et][dst[j]], 1);
        }
    }
}

// ---------------- CSR scans ----------------
__global__ void k_scan1() {
    int et = blockIdx.y;
    __shared__ int s[1024];
    int i = blockIdx.x * 1024 + threadIdx.x;
    int v = (i < NN) ? g_cnt[et][i] : 0;
    if (i < NN) g_cnt[et][i] = 0;        // reset for next graph replay
    s[threadIdx.x] = v;
    __syncthreads();
    for (int o = 1; o < 1024; o <<= 1) {
        int t = (threadIdx.x >= (unsigned)o) ? s[threadIdx.x - o] : 0;
        __syncthreads();
        s[threadIdx.x] += t;
        __syncthreads();
    }
    if (i < NN) g_rowptr[et][i + 1] = s[threadIdx.x];
    if (threadIdx.x == 1023) g_bsums[et][blockIdx.x] = s[1023];   // raw block total
    if (i == 0) g_rowptr[et][0] = 0;
}

__global__ void k_scan3() {
    int et = blockIdx.y;
    int bx = blockIdx.x;
    __shared__ int partial[128];
    __shared__ int soff;
    if (threadIdx.x < 128)
        partial[threadIdx.x] = (threadIdx.x < bx) ? g_bsums[et][threadIdx.x] : 0;
    __syncthreads();
    if (threadIdx.x < 64) partial[threadIdx.x] += partial[threadIdx.x + 64];
    __syncthreads();
    if (threadIdx.x < 32) {
        int v = partial[threadIdx.x] + partial[threadIdx.x + 32];
#pragma unroll
        for (int o = 16; o; o >>= 1) v += __shfl_down_sync(0xffffffffu, v, o);
        if (threadIdx.x == 0) soff = v;
    }
    __syncthreads();
    int off = soff;
    int i = bx * 1024 + threadIdx.x;
    if (i < NN) g_rowptr[et][i + 1] += off;
}

// ---------------- fill: atomic-free scatter via precomputed ranks ----------------
__global__ void k_fill2(const int* __restrict__ s0, const int* __restrict__ d0,
                        const int* __restrict__ s1, const int* __restrict__ d1) {
    int et = blockIdx.y;
    const int* src = et ? s1 : s0;
    const int* dst = et ? d1 : d0;
    int base = blockIdx.x * 1024 + threadIdx.x * 4;
    if (base + 4 <= NE) {
        int4 s4 = *(const int4*)(src + base);
        int4 d4 = *(const int4*)(dst + base);
        int4 r4 = *(const int4*)(g_rank[et] + base);
        g_colv[et][g_rowptr[et][d4.x] + r4.x] = s4.x;
        g_colv[et][g_rowptr[et][d4.y] + r4.y] = s4.y;
        g_colv[et][g_rowptr[et][d4.z] + r4.z] = s4.z;
        g_colv[et][g_rowptr[et][d4.w] + r4.w] = s4.w;
    } else {
        for (int j = base; j < base + 4 && j < NE; j++)
            g_colv[et][g_rowptr[et][dst[j]] + g_rank[et][j]] = src[j];
    }
}

// ---------------- mean aggregation (broadcast indices, 4-deep) ----------------
__global__ void __launch_bounds__(256) k_agg2(int shu, int shi) {
    int et = blockIdx.y;
    const H4* __restrict__ hv = (const H4*)g_hsh[et == 0 ? shu : shi];
    H4* __restrict__ outp = (H4*)g_aggh[et];
    int gw = (blockIdx.x * 256 + threadIdx.x) >> 5;
    int lane = threadIdx.x & 31;
    if (gw >= NN) return;
    int beg = g_rowptr[et][gw], end = g_rowptr[et][gw + 1];
    float ax = 0.f, ay = 0.f, az = 0.f, aw = 0.f;
    int e = beg;
    for (; e + 4 <= end; e += 4) {
        int s0 = g_colv[et][e], s1 = g_colv[et][e + 1];
        int s2 = g_colv[et][e + 2], s3 = g_colv[et][e + 3];
        H4 v0 = hv[s0 * 32 + lane], v1 = hv[s1 * 32 + lane];
        H4 v2 = hv[s2 * 32 + lane], v3 = hv[s3 * 32 + lane];
        float2 f0a = __half22float2(v0.a), f0b = __half22float2(v0.b);
        float2 f1a = __half22float2(v1.a), f1b = __half22float2(v1.b);
        float2 f2a = __half22float2(v2.a), f2b = __half22float2(v2.b);
        float2 f3a = __half22float2(v3.a), f3b = __half22float2(v3.b);
        ax += (f0a.x + f1a.x) + (f2a.x + f3a.x);
        ay += (f0a.y + f1a.y) + (f2a.y + f3a.y);
        az += (f0b.x + f1b.x) + (f2b.x + f3b.x);
        aw += (f0b.y + f1b.y) + (f2b.y + f3b.y);
    }
    for (; e < end; e++) {
        int s0 = g_colv[et][e];
        H4 v = hv[s0 * 32 + lane];
        float2 fa = __half22float2(v.a), fb = __half22float2(v.b);
        ax += fa.x; ay += fa.y; az += fb.x; aw += fb.y;
    }
    float invc = 1.0f / fmaxf((float)(end - beg), 1.0f);
    H4 o;
    o.a = __floats2half2_rn(ax * invc, ay * invc);
    o.b = __floats2half2_rn(az * invc, aw * invc);
    outp[gw * 32 + lane] = o;
}

// ---------------- GEMM param set ----------------
struct GP {
    const float* bias;
    const float* bng; const float* bnb; const float* bnm; const float* bnv;
    const float* W2; const float* b2;
    float* out2;
    int a1, a2, wt, res, sh;
};

// ---------------- fp16 HMMA GEMM, 512 threads, 4x4 warp grid ----------------
// MODE 0: shadow = relu(A1@W + bias)                  (K=128, N=128)
// MODE 1: hid = relu(A1@W + b1) in smem; out2 = hid@W2 + b2   (K=128, N=64; cls fused)
// MODE 2: m = rownorm(A1@Wl + A2@Wr + bias); shadow = relu(bn(m + res))  (K=256, N=128)
template <int MODE, int NT>
__global__ void __launch_bounds__(512, 2) k_g3(GP pa, GP pb) {
    constexpr int NST = (MODE == 2) ? 8 : 4;
    constexpr int KTOT = NST * 32;
    constexpr int NW = NT * 32;
    constexpr int NSPAN = NT * 8;

    extern __shared__ char smc[];
    __half* Ws = (__half*)smc;              // [2][NW][40]
    __half* As = Ws + 2 * NW * 40;          // [2][128][40]
    float* red = (float*)(As + 2 * 128 * 40);   // [128][4]
    __half* hid = (__half*)smc;             // MODE1: [128][72]
    float* W2s = (float*)((char*)red + 2048 + 512);
    float* b2s = W2s + HMID * OUTC;

    GP P = blockIdx.y ? pb : pa;
    const __half* A1 = pickh(P.a1);
    const __half* A2 = (MODE == 2) ? pickh(P.a2) : nullptr;
    const __half* resh = (MODE == 2) ? pickh(P.res) : nullptr;
    __half* hsh = (P.sh >= 0) ? g_hsh[P.sh] : nullptr;
    const __half* Wt = g_wh + P.wt;

    int tid = threadIdx.x, lane = tid & 31, w = tid >> 5;
    int wm = w & 3, wn = w >> 2;
    int p = lane >> 2, q = lane & 3;
    uint32_t ws_u = (uint32_t)__cvta_generic_to_shared(Ws);
    uint32_t as_u = (uint32_t)__cvta_generic_to_shared(As);
    int rowbase = blockIdx.x * TILE_M;

    if (MODE == 1) {
#pragma unroll
        for (int i = tid; i < HMID * OUTC; i += 512) W2s[i] = P.W2[i];
        if (tid < OUTC) b2s[tid] = P.b2[tid];
    }

    int sub = lane >> 3, r8 = lane & 7;
    uint32_t aoff[2];
#pragma unroll
    for (int mt = 0; mt < 2; mt++) {
        int row = wm * 32 + mt * 16 + (sub & 1) * 8 + r8;
        aoff[mt] = (uint32_t)(row * 80 + (sub >> 1) * 16);
    }
    uint32_t boff[NT / 2];
#pragma unroll
    for (int j = 0; j < NT / 2; j++) {
        int n = wn * NSPAN + j * 16 + (sub >> 1) * 8 + r8;
        boff[j] = (uint32_t)(n * 80 + (sub & 1) * 16);
    }

    int arow = tid >> 2, apart = tid & 3;
    int ag = rowbase + arow; if (ag >= NN) ag = NN - 1;

    auto stage = [&](int buf, int s) {
        const __half* Asrc = (MODE == 2 && s >= 4) ? A2 : A1;
        int ks = (s & 3) * 32;
        cp16(as_u + (uint32_t)((buf * 128 + arow) * 80 + apart * 16),
             Asrc + (size_t)ag * H + ks + apart * 8);
        if (NW * 4 >= 512 || tid < NW * 4) {
            int n = tid >> 2, part = tid & 3;
            cp16(ws_u + (uint32_t)((buf * NW + n) * 80 + part * 16),
                 Wt + (size_t)n * KTOT + s * 32 + part * 8);
        }
    };

    float acc[2][NT][4];
#pragma unroll
    for (int mt = 0; mt < 2; mt++)
#pragma unroll
        for (int nt = 0; nt < NT; nt++)
#pragma unroll
            for (int e = 0; e < 4; e++) acc[mt][nt][e] = 0.f;

    stage(0, 0);
    asm volatile("cp.async.commit_group;");

#pragma unroll 1
    for (int s = 0; s < NST; s++) {
        if (s + 1 < NST) {
            stage((s + 1) & 1, s + 1);
            asm volatile("cp.async.commit_group;");
            asm volatile("cp.async.wait_group 1;");
        } else {
            asm volatile("cp.async.wait_group 0;");
        }
        __syncthreads();
        uint32_t abase = as_u + (uint32_t)((s & 1) * 128 * 80);
        uint32_t wbase = ws_u + (uint32_t)((s & 1) * NW * 80);
#pragma unroll
        for (int cc = 0; cc < 2; cc++) {
            uint32_t klb = (uint32_t)(cc * 32);
            uint32_t a[2][4];
#pragma unroll
            for (int mt = 0; mt < 2; mt++)
                ldsm4(a[mt][0], a[mt][1], a[mt][2], a[mt][3], abase + aoff[mt] + klb);
            uint32_t b[NT][2];
#pragma unroll
            for (int j = 0; j < NT / 2; j++)
                ldsm4(b[2 * j][0], b[2 * j][1], b[2 * j + 1][0], b[2 * j + 1][1],
                      wbase + boff[j] + klb);
#pragma unroll
            for (int mt = 0; mt < 2; mt++)
#pragma unroll
                for (int nt = 0; nt < NT; nt++)
                    mma_f16(acc[mt][nt], a[mt], b[nt]);
        }
        __syncthreads();
    }

    // ---------------- epilogue ----------------
#pragma unroll
    for (int nt = 0; nt < NT; nt++) {
        int c = wn * NSPAN + nt * 8 + 2 * q;
        float b0 = __ldg(&P.bias[c]), b1 = __ldg(&P.bias[c + 1]);
        acc[0][nt][0] += b0; acc[0][nt][1] += b1; acc[0][nt][2] += b0; acc[0][nt][3] += b1;
        acc[1][nt][0] += b0; acc[1][nt][1] += b1; acc[1][nt][2] += b0; acc[1][nt][3] += b1;
    }

    if (MODE == 0) {
#pragma unroll
        for (int mt = 0; mt < 2; mt++)
#pragma unroll
            for (int rs = 0; rs < 2; rs++) {
                int r = rowbase + wm * 32 + mt * 16 + p + rs * 8;
                if (r < NN) {
#pragma unroll
                    for (int nt = 0; nt < NT; nt++) {
                        int c = wn * NSPAN + nt * 8 + 2 * q;
                        float o0 = fmaxf(acc[mt][nt][rs * 2], 0.f);
                        float o1 = fmaxf(acc[mt][nt][rs * 2 + 1], 0.f);
                        *(__half2*)&hsh[(size_t)r * H + c] = __floats2half2_rn(o0, o1);
                    }
                }
            }
    } else if (MODE == 1) {
#pragma unroll
        for (int mt = 0; mt < 2; mt++)
#pragma unroll
            for (int rs = 0; rs < 2; rs++) {
                int lr = wm * 32 + mt * 16 + p + rs * 8;
#pragma unroll
                for (int nt = 0; nt < NT; nt++) {
                    int c = wn * NSPAN + nt * 8 + 2 * q;
                    float o0 = fmaxf(acc[mt][nt][rs * 2], 0.f);
                    float o1 = fmaxf(acc[mt][nt][rs * 2 + 1], 0.f);
                    *(__half2*)&hid[lr * 72 + c] = __floats2half2_rn(o0, o1);
                }
            }
        __syncthreads();
        {
            int row = tid >> 2;
            int cg = (tid & 3) * 8;
            float a2[8];
#pragma unroll
            for (int j = 0; j < 8; j++) a2[j] = b2s[cg + j];
#pragma unroll 4
            for (int k = 0; k < HMID; k++) {
                float hv = __half2float(hid[row * 72 + k]);
                const float* wr = &W2s[k * OUTC + cg];
#pragma unroll
                for (int j = 0; j < 8; j++) a2[j] = fmaf(hv, wr[j], a2[j]);
            }
            int r = rowbase + row;
            if (r < NN) {
                *(float4*)&P.out2[(size_t)r * OUTC + cg] =
                    make_float4(a2[0], a2[1], a2[2], a2[3]);
                *(float4*)&P.out2[(size_t)r * OUTC + cg + 4] =
                    make_float4(a2[4], a2[5], a2[6], a2[7]);
            }
        }
    } else {
        float ss[2][2];
#pragma unroll
        for (int mt = 0; mt < 2; mt++) {
            ss[mt][0] = 0.f; ss[mt][1] = 0.f;
#pragma unroll
            for (int nt = 0; nt < NT; nt++) {
                ss[mt][0] = fmaf(acc[mt][nt][0], acc[mt][nt][0],
                            fmaf(acc[mt][nt][1], acc[mt][nt][1], ss[mt][0]));
                ss[mt][1] = fmaf(acc[mt][nt][2], acc[mt][nt][2],
                            fmaf(acc[mt][nt][3], acc[mt][nt][3], ss[mt][1]));
            }
#pragma unroll
            for (int rs = 0; rs < 2; rs++) {
                ss[mt][rs] += __shfl_xor_sync(0xffffffffu, ss[mt][rs], 1);
                ss[mt][rs] += __shfl_xor_sync(0xffffffffu, ss[mt][rs], 2);
            }
        }
        if (q == 0) {
#pragma unroll
            for (int mt = 0; mt < 2; mt++) {
                red[(wm * 32 + mt * 16 + p) * 4 + wn]     = ss[mt][0];
                red[(wm * 32 + mt * 16 + p + 8) * 4 + wn] = ss[mt][1];
            }
        }
        __syncthreads();
#pragma unroll
        for (int mt = 0; mt < 2; mt++)
#pragma unroll
            for (int rs = 0; rs < 2; rs++) {
                int lr = wm * 32 + mt * 16 + p + rs * 8;
                float tot = (red[lr * 4] + red[lr * 4 + 1]) + (red[lr * 4 + 2] + red[lr * 4 + 3]);
                float inv = 1.0f / fmaxf(sqrtf(tot), 1e-12f);
                int r = rowbase + lr;
                if (r < NN) {
#pragma unroll
                    for (int nt = 0; nt < NT; nt++) {
                        int c = wn * NSPAN + nt * 8 + 2 * q;
                        float s0 = __ldg(&P.bng[c])     * rsqrtf(__ldg(&P.bnv[c]) + 1e-5f);
                        float s1 = __ldg(&P.bng[c + 1]) * rsqrtf(__ldg(&P.bnv[c + 1]) + 1e-5f);
                        float2 h = __half22float2(*(const __half2*)&resh[(size_t)r * H + c]);
                        float t0 = fmaf(acc[mt][nt][rs * 2], inv, h.x);
                        float t1 = fmaf(acc[mt][nt][rs * 2 + 1], inv, h.y);
                        float o0 = fmaxf(fmaf(t0 - __ldg(&P.bnm[c]), s0, __ldg(&P.bnb[c])), 0.f);
                        float o1 = fmaxf(fmaf(t1 - __ldg(&P.bnm[c + 1]), s1, __ldg(&P.bnb[c + 1])), 0.f);
                        *(__half2*)&hsh[(size_t)r * H + c] = __floats2half2_rn(o0, o1);
                    }
                }
            }
    }
}

// ---------------- launch ----------------
extern "C" void kernel_launch(void* const* d_in, const int* in_sizes, int n_in,
                              void* d_out, int out_size) {
    const float* x_user  = (const float*)d_in[0];
    const float* x_item  = (const float*)d_in[1];
    const float* enc_W_u = (const float*)d_in[2];
    const float* enc_b_u = (const float*)d_in[3];
    const float* enc_W_i = (const float*)d_in[4];
    const float* enc_b_i = (const float*)d_in[5];
    const float* Wl_ui = (const float*)d_in[6];
    const float* bl_ui = (const float*)d_in[7];
    const float* Wr_ui = (const float*)d_in[8];
    const float* Wl_iu = (const float*)d_in[9];
    const float* bl_iu = (const float*)d_in[10];
    const float* Wr_iu = (const float*)d_in[11];
    const float* bng_u = (const float*)d_in[12];
    const float* bnb_u = (const float*)d_in[13];
    const float* bnm_u = (const float*)d_in[14];
    const float* bnv_u = (const float*)d_in[15];
    const float* bng_i = (const float*)d_in[16];
    const float* bnb_i = (const float*)d_in[17];
    const float* bnm_i = (const float*)d_in[18];
    const float* bnv_i = (const float*)d_in[19];
    const float* cW1 = (const float*)d_in[20];
    const float* cb1 = (const float*)d_in[21];
    const float* cW2 = (const float*)d_in[22];
    const float* cb2 = (const float*)d_in[23];
    const int* ei_ui = (const int*)d_in[24];
    const int* ei_iu = (const int*)d_in[25];
    float* outp = (float*)d_out;

    const int SMEM8 = (2 * 128 * 40 + 2 * 128 * 40) * 2 + 2048 + 512;
    const int SMEM4 = (2 * 64 * 40 + 2 * 128 * 40) * 2 + 2048 + 512
                    + (HMID * OUTC + OUTC) * 4 + 128;
    cudaFuncSetAttribute(k_g3<0, 4>, cudaFuncAttributeMaxDynamicSharedMemorySize, SMEM8);
    cudaFuncSetAttribute(k_g3<2, 4>, cudaFuncAttributeMaxDynamicSharedMemorySize, SMEM8);
    cudaFuncSetAttribute(k_g3<1, 2>, cudaFuncAttributeMaxDynamicSharedMemorySize, SMEM4);

    const int GG = (NN + TILE_M - 1) / TILE_M;  // 782
    const int SB = (NN + 1023) / 1024;          // 98

    GP z{};
    z.a1 = z.a2 = z.wt = z.res = 0;
    z.sh = -1;

    // 1: front (prep_w + prep_x + hist+rank)  2: scan1  3: scan3  4: fill2 (profiled)
    k_front<<<PW_B + 2 * PX_B + 2 * HI_B, 256>>>(
        Wl_ui, Wr_ui, Wl_iu, Wr_iu, enc_W_u, enc_W_i, cW1,
        x_user, x_item, ei_ui + NE, ei_iu + NE);
    k_scan1<<<dim3(SB, 2), 1024>>>();
    k_scan3<<<dim3(SB, 2), 1024>>>();
    k_fill2<<<dim3(HI_B, 2), 256>>>(ei_ui, ei_ui + NE, ei_iu, ei_iu + NE);

    // encoder GEMM: h_u -> shadow 0, h_i -> shadow 2
    {
        GP pa = z, pb = z;
        pa.a1 = 6; pa.wt = BT_ENC_U; pa.bias = enc_b_u; pa.sh = 0;
        pb.a1 = 7; pb.wt = BT_ENC_I; pb.bias = enc_b_i; pb.sh = 2;
        k_g3<0, 4><<<dim3(GG, 2), 512, SMEM8>>>(pa, pb);
    }

    for (int l = 0; l < NL; l++) {
        int shu_cur = l & 1, shu_next = (l + 1) & 1;
        int shi_cur = 2 + (l & 1), shi_next = 2 + ((l + 1) & 1);

        k_agg2<<<dim3(NN / 8, 2), 256>>>(shu_cur, shi_cur);

        GP pa = z, pb = z;
        pa.a1 = 5; pa.a2 = shi_cur; pa.wt = (l * 2 + 0) * 32768;
        pa.res = shu_cur; pa.sh = shu_next;
        pa.bias = bl_iu + (size_t)l * H;
        pa.bng = bng_u + (size_t)l * H; pa.bnb = bnb_u + (size_t)l * H;
        pa.bnm = bnm_u + (size_t)l * H; pa.bnv = bnv_u + (size_t)l * H;
        pb.a1 = 4; pb.a2 = shu_cur; pb.wt = (l * 2 + 1) * 32768;
        pb.res = shi_cur; pb.sh = shi_next;
        pb.bias = bl_ui + (size_t)l * H;
        pb.bng = bng_i + (size_t)l * H; pb.bnb = bnb_i + (size_t)l * H;
        pb.bnm = bnm_i + (size_t)l * H; pb.bnv = bnv_i + (size_t)l * H;
        k_g3<2, 4><<<dim3(GG, 2), 512, SMEM8>>>(pa, pb);
    }

    // fused classifier
    {
        GP pc = z;
        pc.a1 = (NL & 1); pc.wt = BT_CLS; pc.bias = cb1; pc.sh = -1;
        pc.W2 = cW2; pc.b2 = cb2; pc.out2 = outp;
        k_g3<1, 2><<<dim3(GG, 1), 512, SMEM4>>>(pc, pc);
    }
}

// round 17
// speedup vs baseline: 1.0198x; 1.0198x over previous
#include <cuda_runtime.h>
#include <cuda_fp16.h>
#include <cstdint>

#define NN 100000
#define H 128
#define NE 1600000
#define NL 3
#define OUTC 32
#define HMID 64
#define TILE_M 128
#define GG_C 782

// ---------------- scratch ----------------
__device__ __half g_hsh[4][(size_t)NN * H];    // half h: 0=hu0 1=hu1 2=hi0 3=hi1 (ping-pong)
__device__ __half g_aggh[2][(size_t)NN * H];   // half agg outputs (0: user-src, 1: item-src)
__device__ __half g_xh[2][(size_t)NN * H];     // half x_user / x_item
__device__ __half g_wh[237568];                // transposed half weights [n][k]
#define BT_ENC_U 196608
#define BT_ENC_I 212992
#define BT_CLS   229376

__device__ int g_rowptr[2][NN + 1];
__device__ int g_colv[2][NE];
__device__ int g_cnt[2][NN];                   // zero-initialized at load; re-zeroed by scan1
__device__ int g_cursor[2][NN + 1];
__device__ int g_bsums[2][256];

__device__ __forceinline__ const __half* pickh(int id) {
    if (id < 4) return g_hsh[id];
    if (id < 6) return g_aggh[id - 4];
    return g_xh[id - 6];
}

__device__ __forceinline__ void mma_f16(float c[4], const uint32_t a[4], const uint32_t b[2]) {
    asm volatile(
        "mma.sync.aligned.m16n8k16.row.col.f32.f16.f16.f32 "
        "{%0,%1,%2,%3}, {%4,%5,%6,%7}, {%8,%9}, {%0,%1,%2,%3};"
        : "+f"(c[0]), "+f"(c[1]), "+f"(c[2]), "+f"(c[3])
        : "r"(a[0]), "r"(a[1]), "r"(a[2]), "r"(a[3]), "r"(b[0]), "r"(b[1]));
}
__device__ __forceinline__ void ldsm4(uint32_t& r0, uint32_t& r1, uint32_t& r2, uint32_t& r3,
                                      uint32_t addr) {
    asm volatile("ldmatrix.sync.aligned.m8n8.x4.shared.b16 {%0,%1,%2,%3}, [%4];"
                 : "=r"(r0), "=r"(r1), "=r"(r2), "=r"(r3) : "r"(addr));
}
__device__ __forceinline__ void cp16(uint32_t dst, const void* src) {
    asm volatile("cp.async.ca.shared.global [%0], [%1], 16;" :: "r"(dst), "l"(src));
}

struct H4 { __half2 a, b; };

// ---------------- mega front: prep_w + prep_x + hist ----------------
#define PW_B 928
#define PX_B 12500
#define HI_B 1563
__global__ void __launch_bounds__(256) k_front(
    const float* __restrict__ Wl_ui, const float* __restrict__ Wr_ui,
    const float* __restrict__ Wl_iu, const float* __restrict__ Wr_iu,
    const float* __restrict__ eWu, const float* __restrict__ eWi,
    const float* __restrict__ cW1,
    const float* __restrict__ xu, const float* __restrict__ xi,
    const int* __restrict__ du, const int* __restrict__ di) {
    int b = blockIdx.x, tid = threadIdx.x;
    if (b < PW_B) {
        int idx = b * 256 + tid;
        if (idx >= 237568) return;
        float v;
        if (idx < 196608) {
            int c = idx >> 15, r = idx & 32767, n = r >> 8, k = r & 255;
            int l = c >> 1, side = c & 1;
            const float* WL = side ? Wl_ui : Wl_iu;
            const float* WR = side ? Wr_ui : Wr_iu;
            v = (k < 128) ? WL[l * 16384 + k * 128 + n] : WR[l * 16384 + (k - 128) * 128 + n];
        } else if (idx < 229376) {
            int r = idx - 196608, e = r >> 14, rr = r & 16383, n = rr >> 7, k = rr & 127;
            v = (e ? eWi : eWu)[k * 128 + n];
        } else {
            int r = idx - 229376, n = r >> 7, k = r & 127;
            v = cW1[k * 64 + n];
        }
        g_wh[idx] = __float2half(v);
    } else if (b < PW_B + 2 * PX_B) {
        int bb = b - PW_B;
        int et = bb >= PX_B;
        int i = (bb - et * PX_B) * 256 + tid;
        if (i >= NN * 32) return;
        const float4* src = (const float4*)(et ? xi : xu);
        float4 v = src[i];
        H4 h;
        h.a = __floats2half2_rn(v.x, v.y);
        h.b = __floats2half2_rn(v.z, v.w);
        ((H4*)g_xh[et])[i] = h;
    } else {
        int bb = b - (PW_B + 2 * PX_B);
        int et = bb >= HI_B;
        const int* dst = et ? di : du;
        int base = (bb - et * HI_B) * 1024 + tid * 4;
        if (base + 4 <= NE) {
            int4 d4 = *(const int4*)(dst + base);
            atomicAdd(&g_cnt[et][d4.x], 1);
            atomicAdd(&g_cnt[et][d4.y], 1);
            atomicAdd(&g_cnt[et][d4.z], 1);
            atomicAdd(&g_cnt[et][d4.w], 1);
        } else {
            for (int j = base; j < base + 4 && j < NE; j++)
                atomicAdd(&g_cnt[et][dst[j]], 1);
        }
    }
}

// ---------------- CSR scans ----------------
__global__ void k_scan1() {
    int et = blockIdx.y;
    __shared__ int s[1024];
    int i = blockIdx.x * 1024 + threadIdx.x;
    int v = (i < NN) ? g_cnt[et][i] : 0;
    if (i < NN) g_cnt[et][i] = 0;        // reset for next graph replay
    s[threadIdx.x] = v;
    __syncthreads();
    for (int o = 1; o < 1024; o <<= 1) {
        int t = (threadIdx.x >= (unsigned)o) ? s[threadIdx.x - o] : 0;
        __syncthreads();
        s[threadIdx.x] += t;
        __syncthreads();
    }
    if (i < NN) g_rowptr[et][i + 1] = s[threadIdx.x];
    if (threadIdx.x == 1023) g_bsums[et][blockIdx.x] = s[1023];
    if (i == 0) g_rowptr[et][0] = 0;
}

__global__ void k_scan3() {
    int et = blockIdx.y;
    int bx = blockIdx.x;
    __shared__ int partial[128];
    __shared__ int soff;
    if (threadIdx.x < 128)
        partial[threadIdx.x] = (threadIdx.x < bx) ? g_bsums[et][threadIdx.x] : 0;
    __syncthreads();
    if (threadIdx.x < 64) partial[threadIdx.x] += partial[threadIdx.x + 64];
    __syncthreads();
    if (threadIdx.x < 32) {
        int v = partial[threadIdx.x] + partial[threadIdx.x + 32];
#pragma unroll
        for (int o = 16; o; o >>= 1) v += __shfl_down_sync(0xffffffffu, v, o);
        if (threadIdx.x == 0) soff = v;
    }
    __syncthreads();
    int off = soff;
    int i = bx * 1024 + threadIdx.x;
    if (i < NN) {
        int v = g_rowptr[et][i + 1] + off;
        g_rowptr[et][i + 1] = v;
        g_cursor[et][i + 1] = v;
    }
    if (i == 0) g_cursor[et][0] = 0;
}

// ---------------- mean aggregation (broadcast indices, 4-deep) ----------------
__global__ void __launch_bounds__(256) k_agg2(int shu, int shi) {
    int et = blockIdx.y;
    const H4* __restrict__ hv = (const H4*)g_hsh[et == 0 ? shu : shi];
    H4* __restrict__ outp = (H4*)g_aggh[et];
    int gw = (blockIdx.x * 256 + threadIdx.x) >> 5;
    int lane = threadIdx.x & 31;
    if (gw >= NN) return;
    int beg = g_rowptr[et][gw], end = g_rowptr[et][gw + 1];
    float ax = 0.f, ay = 0.f, az = 0.f, aw = 0.f;
    int e = beg;
    for (; e + 4 <= end; e += 4) {
        int s0 = g_colv[et][e], s1 = g_colv[et][e + 1];
        int s2 = g_colv[et][e + 2], s3 = g_colv[et][e + 3];
        H4 v0 = hv[s0 * 32 + lane], v1 = hv[s1 * 32 + lane];
        H4 v2 = hv[s2 * 32 + lane], v3 = hv[s3 * 32 + lane];
        float2 f0a = __half22float2(v0.a), f0b = __half22float2(v0.b);
        float2 f1a = __half22float2(v1.a), f1b = __half22float2(v1.b);
        float2 f2a = __half22float2(v2.a), f2b = __half22float2(v2.b);
        float2 f3a = __half22float2(v3.a), f3b = __half22float2(v3.b);
        ax += (f0a.x + f1a.x) + (f2a.x + f3a.x);
        ay += (f0a.y + f1a.y) + (f2a.y + f3a.y);
        az += (f0b.x + f1b.x) + (f2b.x + f3b.x);
        aw += (f0b.y + f1b.y) + (f2b.y + f3b.y);
    }
    for (; e < end; e++) {
        int s0 = g_colv[et][e];
        H4 v = hv[s0 * 32 + lane];
        float2 fa = __half22float2(v.a), fb = __half22float2(v.b);
        ax += fa.x; ay += fa.y; az += fb.x; aw += fb.y;
    }
    float invc = 1.0f / fmaxf((float)(end - beg), 1.0f);
    H4 o;
    o.a = __floats2half2_rn(ax * invc, ay * invc);
    o.b = __floats2half2_rn(az * invc, aw * invc);
    outp[gw * 32 + lane] = o;
}

// ---------------- GEMM param set ----------------
struct GP {
    const float* bias;
    const float* bng; const float* bnb; const float* bnm; const float* bnv;
    const float* W2; const float* b2;
    float* out2;
    const int* esrc; const int* edst;   // fused fill edge lists (FF)
    int a1, a2, wt, res, sh;
};

// ---------------- fp16 HMMA GEMM, 512 threads, 4x4 warp grid ----------------
// MODE 0: shadow = relu(A1@W + bias)                  (K=128, N=128)
//   FF: blocks with blockIdx.x >= GG_C instead run CSR fill (independent work).
// MODE 1: hid = relu(A1@W + b1) in smem; out2 = hid@W2 + b2   (K=128, N=64; cls fused)
// MODE 2: m = rownorm(A1@Wl + A2@Wr + bias); shadow = relu(bn(m + res))  (K=256, N=128)
template <int MODE, int NT, bool FF>
__global__ void __launch_bounds__(512, 2) k_g3(GP pa, GP pb) {
    constexpr int NST = (MODE == 2) ? 8 : 4;
    constexpr int KTOT = NST * 32;
    constexpr int NW = NT * 32;
    constexpr int NSPAN = NT * 8;

    GP P = blockIdx.y ? pb : pa;

    if (FF && blockIdx.x >= GG_C) {
        // ---- CSR fill chunk: 512 threads x 4 edges ----
        int et = blockIdx.y;
        const int* src = P.esrc;
        const int* dst = P.edst;
        int base = (blockIdx.x - GG_C) * 2048 + threadIdx.x * 4;
        if (base + 4 <= NE) {
            int4 s4 = *(const int4*)(src + base);
            int4 d4 = *(const int4*)(dst + base);
            int p0 = atomicAdd(&g_cursor[et][d4.x], 1); g_colv[et][p0] = s4.x;
            int p1 = atomicAdd(&g_cursor[et][d4.y], 1); g_colv[et][p1] = s4.y;
            int p2 = atomicAdd(&g_cursor[et][d4.z], 1); g_colv[et][p2] = s4.z;
            int p3 = atomicAdd(&g_cursor[et][d4.w], 1); g_colv[et][p3] = s4.w;
        } else {
            for (int j = base; j < base + 4 && j < NE; j++) {
                int d = dst[j];
                int p = atomicAdd(&g_cursor[et][d], 1);
                g_colv[et][p] = src[j];
            }
        }
        return;
    }

    extern __shared__ char smc[];
    __half* Ws = (__half*)smc;              // [2][NW][40]
    __half* As = Ws + 2 * NW * 40;          // [2][128][40]
    float* red = (float*)(As + 2 * 128 * 40);   // [128][4]
    __half* hid = (__half*)smc;             // MODE1: [128][72]
    float* W2s = (float*)((char*)red + 2048 + 512);
    float* b2s = W2s + HMID * OUTC;

    const __half* A1 = pickh(P.a1);
    const __half* A2 = (MODE == 2) ? pickh(P.a2) : nullptr;
    const __half* resh = (MODE == 2) ? pickh(P.res) : nullptr;
    __half* hsh = (P.sh >= 0) ? g_hsh[P.sh] : nullptr;
    const __half* Wt = g_wh + P.wt;

    int tid = threadIdx.x, lane = tid & 31, w = tid >> 5;
    int wm = w & 3, wn = w >> 2;
    int p = lane >> 2, q = lane & 3;
    uint32_t ws_u = (uint32_t)__cvta_generic_to_shared(Ws);
    uint32_t as_u = (uint32_t)__cvta_generic_to_shared(As);
    int rowbase = blockIdx.x * TILE_M;

    if (MODE == 1) {
#pragma unroll
        for (int i = tid; i < HMID * OUTC; i += 512) W2s[i] = P.W2[i];
        if (tid < OUTC) b2s[tid] = P.b2[tid];
    }

    int sub = lane >> 3, r8 = lane & 7;
    uint32_t aoff[2];
#pragma unroll
    for (int mt = 0; mt < 2; mt++) {
        int row = wm * 32 + mt * 16 + (sub & 1) * 8 + r8;
        aoff[mt] = (uint32_t)(row * 80 + (sub >> 1) * 16);
    }
    uint32_t boff[NT / 2];
#pragma unroll
    for (int j = 0; j < NT / 2; j++) {
        int n = wn * NSPAN + j * 16 + (sub >> 1) * 8 + r8;
        boff[j] = (uint32_t)(n * 80 + (sub & 1) * 16);
    }

    int arow = tid >> 2, apart = tid & 3;
    int ag = rowbase + arow; if (ag >= NN) ag = NN - 1;

    auto stage = [&](int buf, int s) {
        const __half* Asrc = (MODE == 2 && s >= 4) ? A2 : A1;
        int ks = (s & 3) * 32;
        cp16(as_u + (uint32_t)((buf * 128 + arow) * 80 + apart * 16),
             Asrc + (size_t)ag * H + ks + apart * 8);
        if (NW * 4 >= 512 || tid < NW * 4) {
            int n = tid >> 2, part = tid & 3;
            cp16(ws_u + (uint32_t)((buf * NW + n) * 80 + part * 16),
                 Wt + (size_t)n * KTOT + s * 32 + part * 8);
        }
    };

    float acc[2][NT][4];
#pragma unroll
    for (int mt = 0; mt < 2; mt++)
#pragma unroll
        for (int nt = 0; nt < NT; nt++)
#pragma unroll
            for (int e = 0; e < 4; e++) acc[mt][nt][e] = 0.f;

    stage(0, 0);
    asm volatile("cp.async.commit_group;");

#pragma unroll 1
    for (int s = 0; s < NST; s++) {
        if (s + 1 < NST) {
            stage((s + 1) & 1, s + 1);
            asm volatile("cp.async.commit_group;");
            asm volatile("cp.async.wait_group 1;");
        } else {
            asm volatile("cp.async.wait_group 0;");
        }
        __syncthreads();
        uint32_t abase = as_u + (uint32_t)((s & 1) * 128 * 80);
        uint32_t wbase = ws_u + (uint32_t)((s & 1) * NW * 80);
#pragma unroll
        for (int cc = 0; cc < 2; cc++) {
            uint32_t klb = (uint32_t)(cc * 32);
            uint32_t a[2][4];
#pragma unroll
            for (int mt = 0; mt < 2; mt++)
                ldsm4(a[mt][0], a[mt][1], a[mt][2], a[mt][3], abase + aoff[mt] + klb);
            uint32_t b[NT][2];
#pragma unroll
            for (int j = 0; j < NT / 2; j++)
                ldsm4(b[2 * j][0], b[2 * j][1], b[2 * j + 1][0], b[2 * j + 1][1],
                      wbase + boff[j] + klb);
#pragma unroll
            for (int mt = 0; mt < 2; mt++)
#pragma unroll
                for (int nt = 0; nt < NT; nt++)
                    mma_f16(acc[mt][nt], a[mt], b[nt]);
        }
        __syncthreads();
    }

    // ---------------- epilogue ----------------
#pragma unroll
    for (int nt = 0; nt < NT; nt++) {
        int c = wn * NSPAN + nt * 8 + 2 * q;
        float b0 = __ldg(&P.bias[c]), b1 = __ldg(&P.bias[c + 1]);
        acc[0][nt][0] += b0; acc[0][nt][1] += b1; acc[0][nt][2] += b0; acc[0][nt][3] += b1;
        acc[1][nt][0] += b0; acc[1][nt][1] += b1; acc[1][nt][2] += b0; acc[1][nt][3] += b1;
    }

    if (MODE == 0) {
#pragma unroll
        for (int mt = 0; mt < 2; mt++)
#pragma unroll
            for (int rs = 0; rs < 2; rs++) {
                int r = rowbase + wm * 32 + mt * 16 + p + rs * 8;
                if (r < NN) {
#pragma unroll
                    for (int nt = 0; nt < NT; nt++) {
                        int c = wn * NSPAN + nt * 8 + 2 * q;
                        float o0 = fmaxf(acc[mt][nt][rs * 2], 0.f);
                        float o1 = fmaxf(acc[mt][nt][rs * 2 + 1], 0.f);
                        *(__half2*)&hsh[(size_t)r * H + c] = __floats2half2_rn(o0, o1);
                    }
                }
            }
    } else if (MODE == 1) {
#pragma unroll
        for (int mt = 0; mt < 2; mt++)
#pragma unroll
            for (int rs = 0; rs < 2; rs++) {
                int lr = wm * 32 + mt * 16 + p + rs * 8;
#pragma unroll
                for (int nt = 0; nt < NT; nt++) {
                    int c = wn * NSPAN + nt * 8 + 2 * q;
                    float o0 = fmaxf(acc[mt][nt][rs * 2], 0.f);
                    float o1 = fmaxf(acc[mt][nt][rs * 2 + 1], 0.f);
                    *(__half2*)&hid[lr * 72 + c] = __floats2half2_rn(o0, o1);
                }
            }
        __syncthreads();
        {
            int row = tid >> 2;
            int cg = (tid & 3) * 8;
            float a2[8];
#pragma unroll
            for (int j = 0; j < 8; j++) a2[j] = b2s[cg + j];
#pragma unroll 4
            for (int k = 0; k < HMID; k++) {
                float hv = __half2float(hid[row * 72 + k]);
                const float* wr = &W2s[k * OUTC + cg];
#pragma unroll
                for (int j = 0; j < 8; j++) a2[j] = fmaf(hv, wr[j], a2[j]);
            }
            int r = rowbase + row;
            if (r < NN) {
                *(float4*)&P.out2[(size_t)r * OUTC + cg] =
                    make_float4(a2[0], a2[1], a2[2], a2[3]);
                *(float4*)&P.out2[(size_t)r * OUTC + cg + 4] =
                    make_float4(a2[4], a2[5], a2[6], a2[7]);
            }
        }
    } else {
        float ss[2][2];
#pragma unroll
        for (int mt = 0; mt < 2; mt++) {
            ss[mt][0] = 0.f; ss[mt][1] = 0.f;
#pragma unroll
            for (int nt = 0; nt < NT; nt++) {
                ss[mt][0] = fmaf(acc[mt][nt][0], acc[mt][nt][0],
                            fmaf(acc[mt][nt][1], acc[mt][nt][1], ss[mt][0]));
                ss[mt][1] = fmaf(acc[mt][nt][2], acc[mt][nt][2],
                            fmaf(acc[mt][nt][3], acc[mt][nt][3], ss[mt][1]));
            }
#pragma unroll
            for (int rs = 0; rs < 2; rs++) {
                ss[mt][rs] += __shfl_xor_sync(0xffffffffu, ss[mt][rs], 1);
                ss[mt][rs] += __shfl_xor_sync(0xffffffffu, ss[mt][rs], 2);
            }
        }
        if (q == 0) {
#pragma unroll
            for (int mt = 0; mt < 2; mt++) {
                red[(wm * 32 + mt * 16 + p) * 4 + wn]     = ss[mt][0];
                red[(wm * 32 + mt * 16 + p + 8) * 4 + wn] = ss[mt][1];
            }
        }
        __syncthreads();
#pragma unroll
        for (int mt = 0; mt < 2; mt++)
#pragma unroll
            for (int rs = 0; rs < 2; rs++) {
                int lr = wm * 32 + mt * 16 + p + rs * 8;
                float tot = (red[lr * 4] + red[lr * 4 + 1]) + (red[lr * 4 + 2] + red[lr * 4 + 3]);
                float inv = 1.0f / fmaxf(sqrtf(tot), 1e-12f);
                int r = rowbase + lr;
                if (r < NN) {
#pragma unroll
                    for (int nt = 0; nt < NT; nt++) {
                        int c = wn * NSPAN + nt * 8 + 2 * q;
                        float s0 = __ldg(&P.bng[c])     * rsqrtf(__ldg(&P.bnv[c]) + 1e-5f);
                        float s1 = __ldg(&P.bng[c + 1]) * rsqrtf(__ldg(&P.bnv[c + 1]) + 1e-5f);
                        float2 h = __half22float2(*(const __half2*)&resh[(size_t)r * H + c]);
                        float t0 = fmaf(acc[mt][nt][rs * 2], inv, h.x);
                        float t1 = fmaf(acc[mt][nt][rs * 2 + 1], inv, h.y);
                        float o0 = fmaxf(fmaf(t0 - __ldg(&P.bnm[c]), s0, __ldg(&P.bnb[c])), 0.f);
                        float o1 = fmaxf(fmaf(t1 - __ldg(&P.bnm[c + 1]), s1, __ldg(&P.bnb[c + 1])), 0.f);
                        *(__half2*)&hsh[(size_t)r * H + c] = __floats2half2_rn(o0, o1);
                    }
                }
            }
    }
}

// ---------------- launch ----------------
extern "C" void kernel_launch(void* const* d_in, const int* in_sizes, int n_in,
                              void* d_out, int out_size) {
    const float* x_user  = (const float*)d_in[0];
    const float* x_item  = (const float*)d_in[1];
    const float* enc_W_u = (const float*)d_in[2];
    const float* enc_b_u = (const float*)d_in[3];
    const float* enc_W_i = (const float*)d_in[4];
    const float* enc_b_i = (const float*)d_in[5];
    const float* Wl_ui = (const float*)d_in[6];
    const float* bl_ui = (const float*)d_in[7];
    const float* Wr_ui = (const float*)d_in[8];
    const float* Wl_iu = (const float*)d_in[9];
    const float* bl_iu = (const float*)d_in[10];
    const float* Wr_iu = (const float*)d_in[11];
    const float* bng_u = (const float*)d_in[12];
    const float* bnb_u = (const float*)d_in[13];
    const float* bnm_u = (const float*)d_in[14];
    const float* bnv_u = (const float*)d_in[15];
    const float* bng_i = (const float*)d_in[16];
    const float* bnb_i = (const float*)d_in[17];
    const float* bnm_i = (const float*)d_in[18];
    const float* bnv_i = (const float*)d_in[19];
    const float* cW1 = (const float*)d_in[20];
    const float* cb1 = (const float*)d_in[21];
    const float* cW2 = (const float*)d_in[22];
    const float* cb2 = (const float*)d_in[23];
    const int* ei_ui = (const int*)d_in[24];
    const int* ei_iu = (const int*)d_in[25];
    float* outp = (float*)d_out;

    const int SMEM8 = (2 * 128 * 40 + 2 * 128 * 40) * 2 + 2048 + 512;
    const int SMEM4 = (2 * 64 * 40 + 2 * 128 * 40) * 2 + 2048 + 512
                    + (HMID * OUTC + OUTC) * 4 + 128;
    cudaFuncSetAttribute((const void*)k_g3<0, 4, true>,
                         cudaFuncAttributeMaxDynamicSharedMemorySize, SMEM8);
    cudaFuncSetAttribute((const void*)k_g3<2, 4, false>,
                         cudaFuncAttributeMaxDynamicSharedMemorySize, SMEM8);
    cudaFuncSetAttribute((const void*)k_g3<1, 2, false>,
                         cudaFuncAttributeMaxDynamicSharedMemorySize, SMEM4);

    const int GG = GG_C;                        // 782
    const int FB = (NE + 2047) / 2048;          // 782 fill blocks
    const int SB = (NN + 1023) / 1024;          // 98

    GP z{};
    z.a1 = z.a2 = z.wt = z.res = 0;
    z.sh = -1;

    // 1: front  2: scan1  3: scan3  4: enc GEMM + fused fill (profiled)
    k_front<<<PW_B + 2 * PX_B + 2 * HI_B, 256>>>(
        Wl_ui, Wr_ui, Wl_iu, Wr_iu, enc_W_u, enc_W_i, cW1,
        x_user, x_item, ei_ui + NE, ei_iu + NE);
    k_scan1<<<dim3(SB, 2), 1024>>>();
    k_scan3<<<dim3(SB, 2), 1024>>>();

    // encoder GEMM (h_u -> shadow 0, h_i -> shadow 2) + CSR fill overlapped
    {
        GP pa = z, pb = z;
        pa.a1 = 6; pa.wt = BT_ENC_U; pa.bias = enc_b_u; pa.sh = 0;
        pa.esrc = ei_ui; pa.edst = ei_ui + NE;
        pb.a1 = 7; pb.wt = BT_ENC_I; pb.bias = enc_b_i; pb.sh = 2;
        pb.esrc = ei_iu; pb.edst = ei_iu + NE;
        k_g3<0, 4, true><<<dim3(GG + FB, 2), 512, SMEM8>>>(pa, pb);
    }

    for (int l = 0; l < NL; l++) {
        int shu_cur = l & 1, shu_next = (l + 1) & 1;
        int shi_cur = 2 + (l & 1), shi_next = 2 + ((l + 1) & 1);

        k_agg2<<<dim3(NN / 8, 2), 256>>>(shu_cur, shi_cur);

        GP pa = z, pb = z;
        pa.a1 = 5; pa.a2 = shi_cur; pa.wt = (l * 2 + 0) * 32768;
        pa.res = shu_cur; pa.sh = shu_next;
        pa.bias = bl_iu + (size_t)l * H;
        pa.bng = bng_u + (size_t)l * H; pa.bnb = bnb_u + (size_t)l * H;
        pa.bnm = bnm_u + (size_t)l * H; pa.bnv = bnv_u + (size_t)l * H;
        pb.a1 = 4; pb.a2 = shu_cur; pb.wt = (l * 2 + 1) * 32768;
        pb.res = shi_cur; pb.sh = shi_next;
        pb.bias = bl_ui + (size_t)l * H;
        pb.bng = bng_i + (size_t)l * H; pb.bnb = bnb_i + (size_t)l * H;
        pb.bnm = bnm_i + (size_t)l * H; pb.bnv = bnv_i + (size_t)l * H;
        k_g3<2, 4, false><<<dim3(GG, 2), 512, SMEM8>>>(pa, pb);
    }

    // fused classifier
    {
        GP pc = z;
        pc.a1 = (NL & 1); pc.wt = BT_CLS; pc.bias = cb1; pc.sh = -1;
        pc.W2 = cW2; pc.b2 = cb2; pc.out2 = outp;
        k_g3<1, 2, false><<<dim3(GG, 1), 512, SMEM4>>>(pc, pc);
    }
}